// round 17
// baseline (speedup 1.0000x reference)
#include <cuda_runtime.h>
#include <cuda_fp16.h>
#include <cstdint>

#define NNODES 50000
#define NODPAD 50048
#define NEDGES 800000
#define F_IN   128
#define HID    256
#define NOUT   40
#define MTILES (NODPAD / 128)   // 391

// ---------------- scratch (static device memory, no allocations) ------------
// g_cnt / g_total are ZERO at module load and re-zeroed at the end of k_gemm2f.
__device__ int   g_cnt[NNODES];
__device__ int   g_off[NNODES];
__device__ int   g_rank[NEDGES];
__device__ int   g_total;
__device__ float g_dinv[NNODES];
__device__ __align__(16) int2 g_edge[NEDGES];    // (src, weight bits)
__device__ __align__(16) __half g_xh[(size_t)NNODES * F_IN];     // fp16 x
__device__ __align__(16) __half g_h1h[(size_t)NNODES * HID];     // fp16 h1
__device__ __align__(16) __half g_ax[(size_t)NODPAD * F_IN];     // agg(x) fp16
__device__ __align__(16) __half g_a1[(size_t)NODPAD * HID];      // agg(h1) fp16
__device__ __align__(16) __half g_w1h[HID * F_IN];               // W1^T fp16
__device__ __align__(16) __half g_w2h[HID * HID];                // W2^T fp16
__device__ __align__(16) __half g_wchi[NOUT * HID];              // Wc^T hi fp16
__device__ __align__(16) __half g_wclo[NOUT * HID];              // Wc^T lo fp16

// ---------------- fused count + prep ------------------------------------------
__global__ void k_precount(const int* __restrict__ ei,
                           const float* __restrict__ x,
                           const float* __restrict__ W1,
                           const float* __restrict__ W2,
                           const float* __restrict__ Wc)
{
    int i = blockIdx.x * blockDim.x + threadIdx.x;
    if (i < NEDGES) {
        int d = ei[NEDGES + i];
        g_rank[i] = atomicAdd(&g_cnt[d], 1);
    }
    if (i < HID * F_IN) {
        int n = i / F_IN, k = i % F_IN;
        g_w1h[i] = __float2half_rn(W1[k * HID + n]);
    }
    if (i < HID * HID) {
        int n = i / HID, k = i % HID;
        g_w2h[i] = __float2half_rn(W2[k * HID + n]);
    }
    if (i < NOUT * HID) {
        int n = i / HID, k = i % HID;
        float v = Wc[k * NOUT + n];
        __half h = __float2half_rn(v);
        g_wchi[i] = h;
        g_wclo[i] = __float2half_rn(v - __half2float(h));
    }
    #pragma unroll
    for (int q = 0; q < 2; q++) {
        int j = i + q * NEDGES;
        if (j < NNODES * F_IN / 4) {
            float4 v = ((const float4*)x)[j];
            __half2 a = __floats2half2_rn(v.x, v.y);
            __half2 b = __floats2half2_rn(v.z, v.w);
            uint2 u;
            u.x = *(uint32_t*)&a; u.y = *(uint32_t*)&b;
            ((uint2*)g_xh)[j] = u;
        }
    }
}

__global__ void k_offsets()
{
    int i = blockIdx.x * blockDim.x + threadIdx.x;
    int lane = threadIdx.x & 31;
    int c = (i < NNODES) ? g_cnt[i] : 0;
    int sum = c;
    #pragma unroll
    for (int o = 1; o < 32; o <<= 1) {
        int t = __shfl_up_sync(0xFFFFFFFF, sum, o);
        if (lane >= o) sum += t;
    }
    int wtotal = __shfl_sync(0xFFFFFFFF, sum, 31);
    int base;
    if (lane == 31) base = atomicAdd(&g_total, wtotal);
    base = __shfl_sync(0xFFFFFFFF, base, 31);
    if (i < NNODES) {
        g_off[i]  = base + sum - c;
        g_dinv[i] = rsqrtf((float)(c + 1));
    }
}

__global__ void k_scatter(const int* __restrict__ ei)
{
    int e = (blockIdx.x * blockDim.x + threadIdx.x) * 2;
    if (e >= NEDGES) return;
    int2 s2 = *(const int2*)(ei + e);
    int2 d2 = *(const int2*)(ei + NEDGES + e);
    int2 r2 = *(const int2*)(g_rank + e);
    float w0 = g_dinv[s2.x] * g_dinv[d2.x];
    float w1 = g_dinv[s2.y] * g_dinv[d2.y];
    int p0 = g_off[d2.x] + r2.x;
    int p1 = g_off[d2.y] + r2.y;
    g_edge[p0] = make_int2(s2.x, __float_as_int(w0));
    g_edge[p1] = make_int2(s2.y, __float_as_int(w1));
}

// ---------------- sparse aggregation: edge-split across 2 warps per node ------
// F/128 feature slices x 2 edge-half warps per node; smem float4 combine.
// agg_x (F=128): 2 warps/node, 4 nodes/block. agg_h1 (F=256): 4 warps/node, 2 nodes/block.
template <int F>
__device__ __forceinline__ void agg_body(const __half* __restrict__ in,
                                         __half* __restrict__ outp)
{
    constexpr int WPN = F / 128;              // feature slices per node
    constexpr int PAIRS = 4;                  // warp-pairs per 256-thread block
    __shared__ float4 red[PAIRS][32];

    const int wid  = threadIdx.x >> 5;
    const int lane = threadIdx.x & 31;
    const int pair = wid >> 1;                // 0..3
    const int half = wid & 1;                 // edge-half id
    const int node = blockIdx.x * (PAIRS / WPN) + pair / WPN;
    const int slc  = pair % WPN;
    const int coff = slc * 128 + 4 * lane;

    const float dn = g_dinv[node];

    float4 acc = make_float4(0.f, 0.f, 0.f, 0.f);
    if (half == 0) {
        const float w0 = dn * dn;
        uint2 u = __ldg((const uint2*)(in + (size_t)node * F + coff));
        float2 f0 = __half22float2(*(const __half2*)&u.x);
        float2 f1 = __half22float2(*(const __half2*)&u.y);
        acc.x = w0 * f0.x; acc.y = w0 * f0.y;
        acc.z = w0 * f1.x; acc.w = w0 * f1.y;
    }

    const int beg = g_off[node];
    const int cnt = g_cnt[node];
    const int h0  = (cnt + 1) >> 1;
    int i   = beg + (half ? h0 : 0);
    const int end = beg + (half ? cnt : h0);

    for (; i + 4 <= end; i += 4) {
        int2 e[4];
        #pragma unroll
        for (int q = 0; q < 4; q++) e[q] = g_edge[i + q];
        uint2 u[4];
        #pragma unroll
        for (int q = 0; q < 4; q++)
            u[q] = __ldg((const uint2*)(in + (size_t)e[q].x * F + coff));
        #pragma unroll
        for (int q = 0; q < 4; q++) {
            const float we = __int_as_float(e[q].y);
            float2 f0 = __half22float2(*(const __half2*)&u[q].x);
            float2 f1 = __half22float2(*(const __half2*)&u[q].y);
            acc.x += we * f0.x; acc.y += we * f0.y;
            acc.z += we * f1.x; acc.w += we * f1.y;
        }
    }
    for (; i < end; i++) {
        const int2 e0 = g_edge[i];
        const float we = __int_as_float(e0.y);
        uint2 u0 = __ldg((const uint2*)(in + (size_t)e0.x * F + coff));
        float2 f0 = __half22float2(*(const __half2*)&u0.x);
        float2 f1 = __half22float2(*(const __half2*)&u0.y);
        acc.x += we * f0.x; acc.y += we * f0.y;
        acc.z += we * f1.x; acc.w += we * f1.y;
    }

    if (half) red[pair][lane] = acc;
    __syncthreads();
    if (!half) {
        float4 o = red[pair][lane];
        acc.x += o.x; acc.y += o.y; acc.z += o.z; acc.w += o.w;
        __half2 p0 = __floats2half2_rn(acc.x, acc.y);
        __half2 p1 = __floats2half2_rn(acc.z, acc.w);
        uint2 u;
        u.x = *(uint32_t*)&p0; u.y = *(uint32_t*)&p1;
        *(uint2*)(outp + (size_t)node * F + coff) = u;
    }
}

__global__ void __launch_bounds__(256) k_agg_x()  { agg_body<F_IN>(g_xh,  g_ax); }
__global__ void __launch_bounds__(256) k_agg_h1() { agg_body<HID>(g_h1h, g_a1); }

// ---------------- GEMM1: 128x128 tile, 3-stage, 2 blocks/SM -------------------
#define SROWB 80
#define T_STG (128 * SROWB)
#define GEMM_SMEM (6 * T_STG)                // 61440 B

__global__ void __launch_bounds__(256, 2) k_gemm1(const float* __restrict__ bias)
{
    constexpr int F = F_IN;
    const __half* A = g_ax;
    const __half* B = g_w1h;
    __half* C = g_h1h;

    extern __shared__ __align__(16) uint8_t smem_dyn[];
    uint32_t sA;
    asm("{ .reg .u64 t; cvta.to.shared.u64 t, %1; cvt.u32.u64 %0, t; }"
        : "=r"(sA) : "l"(&smem_dyn[0]));
    const uint32_t sB = sA + 3 * T_STG;

    const int tid  = threadIdx.x;
    const int lane = tid & 31;
    const int wid  = tid >> 5;
    const int g    = lane >> 2;
    const int tg   = lane & 3;
    const int wm   = (wid & 1) * 64;
    const int wn   = (wid >> 1) * 32;
    const int brow = blockIdx.y * 128;
    const int bcol = blockIdx.x * 128;

    float acc[4][4][4];
    #pragma unroll
    for (int mi = 0; mi < 4; mi++)
        #pragma unroll
        for (int ni = 0; ni < 4; ni++)
            #pragma unroll
            for (int c = 0; c < 4; c++) acc[mi][ni][c] = 0.f;

    const int lrow = tid >> 2;
    const int lseg = tid & 3;
    auto load_stage = [&](int st, int k0) {
        #pragma unroll
        for (int i = 0; i < 2; i++) {
            int row = lrow + i * 64;
            uint32_t soA = sA + (uint32_t)st * T_STG + row * SROWB + lseg * 16;
            const __half* ga = A + (size_t)(brow + row) * F + k0 + lseg * 8;
            asm volatile("cp.async.cg.shared.global [%0], [%1], 16;"
                         :: "r"(soA), "l"(ga));
            uint32_t soB = sB + (uint32_t)st * T_STG + row * SROWB + lseg * 16;
            const __half* gb = B + (size_t)(bcol + row) * F + k0 + lseg * 8;
            asm volatile("cp.async.cg.shared.global [%0], [%1], 16;"
                         :: "r"(soB), "l"(gb));
        }
        asm volatile("cp.async.commit_group;");
    };

    constexpr int NK = F / 32;
    load_stage(0, 0);
    load_stage(1, 32);

    const int lr  = lane & 15;
    const int lhi = (lane >> 4) * 16;

    int st = 0;
    for (int ki = 0; ki < NK; ki++) {
        if (ki + 1 < NK) asm volatile("cp.async.wait_group 1;");
        else             asm volatile("cp.async.wait_group 0;");
        __syncthreads();
        if (ki + 2 < NK) {
            int st2 = st + 2; if (st2 >= 3) st2 -= 3;
            load_stage(st2, (ki + 2) * 32);
        }
        const uint32_t bufA = sA + st * T_STG;
        const uint32_t bufB = sB + st * T_STG;

        #pragma unroll
        for (int kk = 0; kk < 2; kk++) {
            const uint32_t kb = kk * 32;
            uint32_t af[4][4];
            #pragma unroll
            for (int mi = 0; mi < 4; mi++) {
                uint32_t addr = bufA + (wm + mi * 16 + lr) * SROWB + kb + lhi;
                asm volatile("ldmatrix.sync.aligned.m8n8.x4.shared.b16 {%0,%1,%2,%3}, [%4];"
                             : "=r"(af[mi][0]), "=r"(af[mi][1]),
                               "=r"(af[mi][2]), "=r"(af[mi][3]) : "r"(addr));
            }
            #pragma unroll
            for (int p = 0; p < 2; p++) {
                uint32_t r0, r1, r2, r3;
                uint32_t addr = bufB + (wn + p * 16 + lr) * SROWB + kb + lhi;
                asm volatile("ldmatrix.sync.aligned.m8n8.x4.shared.b16 {%0,%1,%2,%3}, [%4];"
                             : "=r"(r0), "=r"(r1), "=r"(r2), "=r"(r3) : "r"(addr));
                #pragma unroll
                for (int mi = 0; mi < 4; mi++) {
                    asm volatile(
                        "mma.sync.aligned.m16n8k16.row.col.f32.f16.f16.f32 "
                        "{%0,%1,%2,%3},{%4,%5,%6,%7},{%8,%9},{%0,%1,%2,%3};"
                        : "+f"(acc[mi][2 * p][0]), "+f"(acc[mi][2 * p][1]),
                          "+f"(acc[mi][2 * p][2]), "+f"(acc[mi][2 * p][3])
                        : "r"(af[mi][0]), "r"(af[mi][1]), "r"(af[mi][2]), "r"(af[mi][3]),
                          "r"(r0), "r"(r2));
                    asm volatile(
                        "mma.sync.aligned.m16n8k16.row.col.f32.f16.f16.f32 "
                        "{%0,%1,%2,%3},{%4,%5,%6,%7},{%8,%9},{%0,%1,%2,%3};"
                        : "+f"(acc[mi][2 * p + 1][0]), "+f"(acc[mi][2 * p + 1][1]),
                          "+f"(acc[mi][2 * p + 1][2]), "+f"(acc[mi][2 * p + 1][3])
                        : "r"(af[mi][0]), "r"(af[mi][1]), "r"(af[mi][2]), "r"(af[mi][3]),
                          "r"(r1), "r"(r3));
                }
            }
        }
        if (++st == 3) st = 0;
    }

    #pragma unroll
    for (int ni = 0; ni < 4; ni++) {
        const int col = bcol + wn + ni * 8 + tg * 2;
        const float b0 = __ldg(bias + col);
        const float b1 = __ldg(bias + col + 1);
        #pragma unroll
        for (int mi = 0; mi < 4; mi++) {
            int r0 = brow + wm + mi * 16 + g;
            if (r0 < NNODES) {
                __half2 o = __floats2half2_rn(fmaxf(acc[mi][ni][0] + b0, 0.f),
                                              fmaxf(acc[mi][ni][1] + b1, 0.f));
                *(__half2*)(C + (size_t)r0 * HID + col) = o;
            }
            int r1 = r0 + 8;
            if (r1 < NNODES) {
                __half2 o = __floats2half2_rn(fmaxf(acc[mi][ni][2] + b0, 0.f),
                                              fmaxf(acc[mi][ni][3] + b1, 0.f));
                *(__half2*)(C + (size_t)r1 * HID + col) = o;
            }
        }
    }
}

// ---------------- GEMM2 + classifier fused (+ counter cleanup) ----------------
#define A_STG2 10240
#define B_STG2 20480
#define H2ROWB 528
#define H2S_OFF 0
#define WHI_OFF (128 * H2ROWB)
#define WLO_OFF (WHI_OFF + 64 * H2ROWB)
#define GEMM2_SMEM (WLO_OFF + 64 * H2ROWB)   // 135168

__global__ void __launch_bounds__(256) k_gemm2f(const float* __restrict__ b2,
                                                const float* __restrict__ bc,
                                                float* __restrict__ out)
{
    constexpr int F = HID;
    const __half* A = g_a1;
    const __half* B = g_w2h;

    extern __shared__ __align__(16) uint8_t smem_dyn[];
    uint32_t sbase;
    asm("{ .reg .u64 t; cvta.to.shared.u64 t, %1; cvt.u32.u64 %0, t; }"
        : "=r"(sbase) : "l"(&smem_dyn[0]));
    const uint32_t sA = sbase;
    const uint32_t sB = sbase + 3 * A_STG2;

    const int tid  = threadIdx.x;
    const int lane = tid & 31;
    const int wid  = tid >> 5;
    const int g    = lane >> 2;
    const int tg   = lane & 3;
    const int wm   = (wid & 1) * 64;
    const int wn   = (wid >> 1) * 64;
    const int brow = blockIdx.x * 128;

    float acc[4][8][4];
    #pragma unroll
    for (int mi = 0; mi < 4; mi++)
        #pragma unroll
        for (int ni = 0; ni < 8; ni++)
            #pragma unroll
            for (int c = 0; c < 4; c++) acc[mi][ni][c] = 0.f;

    const int lrow = tid >> 2;
    const int lseg = tid & 3;
    auto load_stage = [&](int st, int k0) {
        #pragma unroll
        for (int i = 0; i < 2; i++) {
            int row = lrow + i * 64;
            uint32_t soA = sA + (uint32_t)st * A_STG2 + row * SROWB + lseg * 16;
            const __half* ga = A + (size_t)(brow + row) * F + k0 + lseg * 8;
            asm volatile("cp.async.cg.shared.global [%0], [%1], 16;"
                         :: "r"(soA), "l"(ga));
        }
        #pragma unroll
        for (int i = 0; i < 4; i++) {
            int row = lrow + i * 64;
            uint32_t soB = sB + (uint32_t)st * B_STG2 + row * SROWB + lseg * 16;
            const __half* gb = B + (size_t)row * F + k0 + lseg * 8;
            asm volatile("cp.async.cg.shared.global [%0], [%1], 16;"
                         :: "r"(soB), "l"(gb));
        }
        asm volatile("cp.async.commit_group;");
    };

    constexpr int NK = F / 32;   // 8
    load_stage(0, 0);
    load_stage(1, 32);

    const int lr  = lane & 15;
    const int lhi = (lane >> 4) * 16;

    int st = 0;
    for (int ki = 0; ki < NK; ki++) {
        if (ki + 1 < NK) asm volatile("cp.async.wait_group 1;");
        else             asm volatile("cp.async.wait_group 0;");
        __syncthreads();
        if (ki + 2 < NK) {
            int st2 = st + 2; if (st2 >= 3) st2 -= 3;
            load_stage(st2, (ki + 2) * 32);
        }
        const uint32_t bufA = sA + st * A_STG2;
        const uint32_t bufB = sB + st * B_STG2;

        #pragma unroll
        for (int kk = 0; kk < 2; kk++) {
            const uint32_t kb = kk * 32;
            uint32_t af[4][4];
            #pragma unroll
            for (int mi = 0; mi < 4; mi++) {
                uint32_t addr = bufA + (wm + mi * 16 + lr) * SROWB + kb + lhi;
                asm volatile("ldmatrix.sync.aligned.m8n8.x4.shared.b16 {%0,%1,%2,%3}, [%4];"
                             : "=r"(af[mi][0]), "=r"(af[mi][1]),
                               "=r"(af[mi][2]), "=r"(af[mi][3]) : "r"(addr));
            }
            #pragma unroll
            for (int p = 0; p < 4; p++) {
                uint32_t r0, r1, r2, r3;
                uint32_t addr = bufB + (wn + p * 16 + lr) * SROWB + kb + lhi;
                asm volatile("ldmatrix.sync.aligned.m8n8.x4.shared.b16 {%0,%1,%2,%3}, [%4];"
                             : "=r"(r0), "=r"(r1), "=r"(r2), "=r"(r3) : "r"(addr));
                #pragma unroll
                for (int mi = 0; mi < 4; mi++) {
                    asm volatile(
                        "mma.sync.aligned.m16n8k16.row.col.f32.f16.f16.f32 "
                        "{%0,%1,%2,%3},{%4,%5,%6,%7},{%8,%9},{%0,%1,%2,%3};"
                        : "+f"(acc[mi][2 * p][0]), "+f"(acc[mi][2 * p][1]),
                          "+f"(acc[mi][2 * p][2]), "+f"(acc[mi][2 * p][3])
                        : "r"(af[mi][0]), "r"(af[mi][1]), "r"(af[mi][2]), "r"(af[mi][3]),
                          "r"(r0), "r"(r2));
                    asm volatile(
                        "mma.sync.aligned.m16n8k16.row.col.f32.f16.f16.f32 "
                        "{%0,%1,%2,%3},{%4,%5,%6,%7},{%8,%9},{%0,%1,%2,%3};"
                        : "+f"(acc[mi][2 * p + 1][0]), "+f"(acc[mi][2 * p + 1][1]),
                          "+f"(acc[mi][2 * p + 1][2]), "+f"(acc[mi][2 * p + 1][3])
                        : "r"(af[mi][0]), "r"(af[mi][1]), "r"(af[mi][2]), "r"(af[mi][3]),
                          "r"(r1), "r"(r3));
                }
            }
        }
        if (++st == 3) st = 0;
    }
    __syncthreads();

    // ---- epilogue 1: h2 = relu(acc + b2) -> smem fp16 tile [128][264] ----
    __half* h2s = (__half*)(smem_dyn + H2S_OFF);
    #pragma unroll
    for (int ni = 0; ni < 8; ni++) {
        const int col = wn + ni * 8 + tg * 2;
        const float b0 = __ldg(b2 + col);
        const float b1 = __ldg(b2 + col + 1);
        #pragma unroll
        for (int mi = 0; mi < 4; mi++) {
            int r0 = wm + mi * 16 + g;
            __half2 o0 = __floats2half2_rn(fmaxf(acc[mi][ni][0] + b0, 0.f),
                                           fmaxf(acc[mi][ni][1] + b1, 0.f));
            *(__half2*)(h2s + r0 * 264 + col) = o0;
            __half2 o1 = __floats2half2_rn(fmaxf(acc[mi][ni][2] + b0, 0.f),
                                           fmaxf(acc[mi][ni][3] + b1, 0.f));
            *(__half2*)(h2s + (r0 + 8) * 264 + col) = o1;
        }
    }
    {
        __half* whi = (__half*)(smem_dyn + WHI_OFF);
        __half* wlo = (__half*)(smem_dyn + WLO_OFF);
        for (int i = tid; i < NOUT * HID / 8; i += 256) {
            int n = (i * 8) / HID, k = (i * 8) % HID;
            *(uint4*)(whi + n * 264 + k) = *(const uint4*)(g_wchi + n * HID + k);
            *(uint4*)(wlo + n * 264 + k) = *(const uint4*)(g_wclo + n * HID + k);
        }
    }
    __syncthreads();

    // ---- epilogue 2: out = h2s @ Wc^T (hi + lo), HMMA, K=256 ----
    float oacc[6][4];
    #pragma unroll
    for (int ni = 0; ni < 6; ni++)
        #pragma unroll
        for (int c = 0; c < 4; c++) oacc[ni][c] = 0.f;

    const uint32_t h2a = sbase + H2S_OFF;
    const uint32_t wha = sbase + WHI_OFF;
    const uint32_t wla = sbase + WLO_OFF;
    const int mrow = wid * 16;

    #pragma unroll
    for (int kk = 0; kk < 16; kk++) {
        uint32_t a0, a1, a2, a3;
        uint32_t addrA = h2a + (mrow + lr) * H2ROWB + kk * 32 + lhi;
        asm volatile("ldmatrix.sync.aligned.m8n8.x4.shared.b16 {%0,%1,%2,%3}, [%4];"
                     : "=r"(a0), "=r"(a1), "=r"(a2), "=r"(a3) : "r"(addrA));
        #pragma unroll
        for (int p = 0; p < 3; p++) {
            uint32_t r0, r1, r2, r3;
            uint32_t addrB = wha + (p * 16 + lr) * H2ROWB + kk * 32 + lhi;
            asm volatile("ldmatrix.sync.aligned.m8n8.x4.shared.b16 {%0,%1,%2,%3}, [%4];"
                         : "=r"(r0), "=r"(r1), "=r"(r2), "=r"(r3) : "r"(addrB));
            asm volatile(
                "mma.sync.aligned.m16n8k16.row.col.f32.f16.f16.f32 "
                "{%0,%1,%2,%3},{%4,%5,%6,%7},{%8,%9},{%0,%1,%2,%3};"
                : "+f"(oacc[2 * p][0]), "+f"(oacc[2 * p][1]),
                  "+f"(oacc[2 * p][2]), "+f"(oacc[2 * p][3])
                : "r"(a0), "r"(a1), "r"(a2), "r"(a3), "r"(r0), "r"(r2));
            asm volatile(
                "mma.sync.aligned.m16n8k16.row.col.f32.f16.f16.f32 "
                "{%0,%1,%2,%3},{%4,%5,%6,%7},{%8,%9},{%0,%1,%2,%3};"
                : "+f"(oacc[2 * p + 1][0]), "+f"(oacc[2 * p + 1][1]),
                  "+f"(oacc[2 * p + 1][2]), "+f"(oacc[2 * p + 1][3])
                : "r"(a0), "r"(a1), "r"(a2), "r"(a3), "r"(r1), "r"(r3));
            uint32_t addrL = wla + (p * 16 + lr) * H2ROWB + kk * 32 + lhi;
            asm volatile("ldmatrix.sync.aligned.m8n8.x4.shared.b16 {%0,%1,%2,%3}, [%4];"
                         : "=r"(r0), "=r"(r1), "=r"(r2), "=r"(r3) : "r"(addrL));
            asm volatile(
                "mma.sync.aligned.m16n8k16.row.col.f32.f16.f16.f32 "
                "{%0,%1,%2,%3},{%4,%5,%6,%7},{%8,%9},{%0,%1,%2,%3};"
                : "+f"(oacc[2 * p][0]), "+f"(oacc[2 * p][1]),
                  "+f"(oacc[2 * p][2]), "+f"(oacc[2 * p][3])
                : "r"(a0), "r"(a1), "r"(a2), "r"(a3), "r"(r0), "r"(r2));
            asm volatile(
                "mma.sync.aligned.m16n8k16.row.col.f32.f16.f16.f32 "
                "{%0,%1,%2,%3},{%4,%5,%6,%7},{%8,%9},{%0,%1,%2,%3};"
                : "+f"(oacc[2 * p + 1][0]), "+f"(oacc[2 * p + 1][1]),
                  "+f"(oacc[2 * p + 1][2]), "+f"(oacc[2 * p + 1][3])
                : "r"(a0), "r"(a1), "r"(a2), "r"(a3), "r"(r1), "r"(r3));
        }
    }

    #pragma unroll
    for (int ni = 0; ni < 5; ni++) {
        const int col = ni * 8 + tg * 2;
        const float bcl = __ldg(bc + col);
        const float bch = __ldg(bc + col + 1);
        int r0 = brow + mrow + g;
        if (r0 < NNODES) {
            float2 o = make_float2(oacc[ni][0] + bcl, oacc[ni][1] + bch);
            *(float2*)(out + (size_t)r0 * NOUT + col) = o;
        }
        int r1 = r0 + 8;
        if (r1 < NNODES) {
            float2 o = make_float2(oacc[ni][2] + bcl, oacc[ni][3] + bch);
            *(float2*)(out + (size_t)r1 * NOUT + col) = o;
        }
    }

    // ---- cleanup: re-zero counters for the next invocation ----
    {
        int i = blockIdx.x * 256 + tid;
        if (i < NNODES) g_cnt[i] = 0;
        if (i == 0) g_total = 0;
    }
}

// ---------------- launch ------------------------------------------------------
extern "C" void kernel_launch(void* const* d_in, const int* in_sizes, int n_in,
                              void* d_out, int out_size)
{
    const float* x   = (const float*)d_in[0];
    const float* W1  = (const float*)d_in[1];
    const float* b1  = (const float*)d_in[2];
    const float* W2  = (const float*)d_in[3];
    const float* b2  = (const float*)d_in[4];
    const float* Wc  = (const float*)d_in[5];
    const float* bc  = (const float*)d_in[6];
    const int*   ei  = (const int*)  d_in[7];
    float*       out = (float*)d_out;

    cudaFuncSetAttribute(k_gemm1,  cudaFuncAttributeMaxDynamicSharedMemorySize, GEMM_SMEM);
    cudaFuncSetAttribute(k_gemm2f, cudaFuncAttributeMaxDynamicSharedMemorySize, GEMM2_SMEM);

    // fused count + prep (counters zero: static init / previous cleanup)
    k_precount<<<(NEDGES + 255) / 256, 256>>>(ei, x, W1, W2, Wc);
    k_offsets <<<(NNODES + 255) / 256, 256>>>();
    k_scatter <<<(NEDGES / 2 + 255) / 256, 256>>>(ei);

    // layer 1: relu(agg(x) @ W1 + b1) -> fp16 h1   (agg: 2 warps/node, 4 nodes/blk)
    k_agg_x<<<NNODES / 4, 256>>>();
    dim3 g1(HID / 128, MTILES);
    k_gemm1<<<g1, 256, GEMM_SMEM>>>(b1);

    // layer 2 + classifier fused   (agg: 4 warps/node, 2 nodes/blk)
    k_agg_h1<<<NNODES / 2, 256>>>();
    k_gemm2f<<<MTILES, 256, GEMM2_SMEM>>>(b2, bc, out);
}